// round 1
// baseline (speedup 1.0000x reference)
#include <cuda_runtime.h>
#include <cuda_bf16.h>
#include <math.h>

// Problem constants
#define BB    64
#define LL    512
#define DDIM  512
#define HH    8
#define EE    64
#define DFF   2048
#define NMODES 32
#define NAPP  10000
#define KCAT  536    // D + 24
#define TWOPI 6.283185307179586476925286766559

// ---------------------------------------------------------------------------
// Scratch (device globals — no runtime allocation allowed)
// ---------------------------------------------------------------------------
__device__ float g_x [BB*LL*DDIM];      // activations (B,L,D)
__device__ float g_q [BB*LL*DDIM];      // q / foutT / xh
__device__ float g_t1[BB*LL*DDIM];      // qT / g-coefs / fout
__device__ float g_t2[BB*LL*DDIM];      // xs / residual tmp
__device__ float g_y [BB*LL*DFF];       // FFN intermediate (256 MB)
__device__ float g_tw [64*512];         // forward DFT twiddles  [c][l]
__device__ float g_itw[512*64];         // inverse DFT twiddles  [l][c]
__device__ float g_cat[BB*KCAT];        // concat(last, time_vecs[:, -1])

// ---------------------------------------------------------------------------
// Twiddle init (double precision trig)
//   forward:  re_m = sum_l s[l] cos(2pi l m/512);  im_m = -sum_l s[l] sin(...)
//   inverse:  out[l] = re0/512 + sum_{m=1..31} (2 re_m cos - 2 im_m sin)/512
//             (irfft ignores Im(X0) -> coefficient for c==32 is 0)
// ---------------------------------------------------------------------------
__global__ void init_tw_k(float* __restrict__ TW, float* __restrict__ ITW) {
    int i = blockIdx.x * blockDim.x + threadIdx.x;   // 0..32767
    {
        int c = i >> 9, l = i & 511;
        int m = (c < 32) ? c : (c - 32);
        double ang = (TWOPI / 512.0) * (double)(l * m);
        TW[i] = (c < 32) ? (float)cos(ang) : (float)(-sin(ang));
    }
    {
        int l = i >> 6, c = i & 63;
        float v;
        if (c == 0)        v = 1.0f / 512.0f;
        else if (c < 32) { double ang = (TWOPI/512.0) * (double)(l * c);
                           v = (float)(2.0 * cos(ang) / 512.0); }
        else if (c == 32)  v = 0.0f;
        else             { int m = c - 32;
                           double ang = (TWOPI/512.0) * (double)(l * m);
                           v = (float)(-2.0 * sin(ang) / 512.0); }
        ITW[i] = v;
    }
}

// ---------------------------------------------------------------------------
// Embedding: x = app_emb[x_app] + x_time[...,None]*time_w + time_b
// ---------------------------------------------------------------------------
__global__ void embed_k(const int* __restrict__ x_app, const float* __restrict__ x_time,
                        const float* __restrict__ emb, const float* __restrict__ tw,
                        const float* __restrict__ tb, float* __restrict__ x) {
    int b = blockIdx.y, l = blockIdx.x, d = threadIdx.x;
    int a = x_app[b * LL + l];
    float t = x_time[b * LL + l];
    x[((size_t)b * LL + l) * DDIM + d] = emb[(size_t)a * DDIM + d] + t * tw[d] + tb[d];
}

// ---------------------------------------------------------------------------
// Generic GEMM:  C[m,n] = sum_k A[m,k] * B[n,k]  (+bias[n]) (+Cin[m,n]) (relu)
// 128x128 tile, BK=8, 256 threads, 8x8 microtile. Requires K % 8 == 0, N % 8 == 0.
// ---------------------------------------------------------------------------
template <int RELU, int ADDC, int BIAS>
__global__ __launch_bounds__(256, 2)
void gemm_nt_kernel(const float* __restrict__ A, const float* __restrict__ Bm,
                    const float* __restrict__ bias, const float* __restrict__ Cin,
                    float* __restrict__ Cout, int M, int N, int K) {
    __shared__ float As[8][128];
    __shared__ float Bs[8][128];

    const int tid = threadIdx.x;
    const int m0 = blockIdx.y * 128;
    const int n0 = blockIdx.x * 128;
    const int lr = tid >> 1;            // 0..127 tile row
    const int lk = (tid & 1) * 4;       // 0 or 4
    const int tx = tid & 15, ty = tid >> 4;

    const int arow = m0 + lr;
    const int brow = n0 + lr;
    const bool aval = arow < M;
    const bool bval = brow < N;
    const float* Ap = A + (size_t)arow * K + lk;
    const float* Bp = Bm + (size_t)brow * K + lk;

    float acc[8][8];
#pragma unroll
    for (int i = 0; i < 8; i++)
#pragma unroll
        for (int j = 0; j < 8; j++) acc[i][j] = 0.f;

    const float4 z4 = make_float4(0.f, 0.f, 0.f, 0.f);
    for (int k0 = 0; k0 < K; k0 += 8) {
        float4 a = aval ? *(const float4*)Ap : z4;
        float4 b = bval ? *(const float4*)Bp : z4;
        Ap += 8; Bp += 8;
        __syncthreads();
        As[lk + 0][lr] = a.x; As[lk + 1][lr] = a.y; As[lk + 2][lr] = a.z; As[lk + 3][lr] = a.w;
        Bs[lk + 0][lr] = b.x; Bs[lk + 1][lr] = b.y; Bs[lk + 2][lr] = b.z; Bs[lk + 3][lr] = b.w;
        __syncthreads();
#pragma unroll
        for (int k = 0; k < 8; k++) {
            float ar[8], br[8];
            *(float4*)&ar[0] = *(const float4*)&As[k][ty * 8];
            *(float4*)&ar[4] = *(const float4*)&As[k][ty * 8 + 4];
            *(float4*)&br[0] = *(const float4*)&Bs[k][tx * 8];
            *(float4*)&br[4] = *(const float4*)&Bs[k][tx * 8 + 4];
#pragma unroll
            for (int i = 0; i < 8; i++)
#pragma unroll
                for (int j = 0; j < 8; j++) acc[i][j] += ar[i] * br[j];
        }
    }

#pragma unroll
    for (int i = 0; i < 8; i++) {
        int m = m0 + ty * 8 + i;
        if (m >= M) continue;
        size_t row = (size_t)m * N;
#pragma unroll
        for (int jg = 0; jg < 8; jg += 4) {
            int n = n0 + tx * 8 + jg;
            if (n >= N) continue;
            float4 v = make_float4(acc[i][jg], acc[i][jg + 1], acc[i][jg + 2], acc[i][jg + 3]);
            if (BIAS) {
                float4 bv = *(const float4*)&bias[n];
                v.x += bv.x; v.y += bv.y; v.z += bv.z; v.w += bv.w;
            }
            if (ADDC) {
                float4 cv = *(const float4*)&Cin[row + n];
                v.x += cv.x; v.y += cv.y; v.z += cv.z; v.w += cv.w;
            }
            if (RELU) {
                v.x = fmaxf(v.x, 0.f); v.y = fmaxf(v.y, 0.f);
                v.z = fmaxf(v.z, 0.f); v.w = fmaxf(v.w, 0.f);
            }
            *(float4*)&Cout[row + n] = v;
        }
    }
}

static void launch_gemm(const float* A, const float* Bm, const float* bias,
                        const float* Cin, float* C, int M, int N, int K,
                        bool relu, bool addc) {
    dim3 grid((N + 127) / 128, (M + 127) / 128);
    if (relu)                      gemm_nt_kernel<1,0,0><<<grid,256>>>(A,Bm,bias,Cin,C,M,N,K);
    else if (addc && bias)         gemm_nt_kernel<0,1,1><<<grid,256>>>(A,Bm,bias,Cin,C,M,N,K);
    else if (addc)                 gemm_nt_kernel<0,1,0><<<grid,256>>>(A,Bm,bias,Cin,C,M,N,K);
    else if (bias)                 gemm_nt_kernel<0,0,1><<<grid,256>>>(A,Bm,bias,Cin,C,M,N,K);
    else                           gemm_nt_kernel<0,0,0><<<grid,256>>>(A,Bm,bias,Cin,C,M,N,K);
}

// ---------------------------------------------------------------------------
// Per-batch 512x512 transpose: out[b][j][i] = in[b][i][j]
// ---------------------------------------------------------------------------
__global__ void transpose512_k(const float* __restrict__ in, float* __restrict__ out) {
    __shared__ float tile[32][33];
    int b = blockIdx.z;
    const float* ip = in + (size_t)b * (512 * 512);
    float* op = out + (size_t)b * (512 * 512);
    int i0 = blockIdx.y * 32, j0 = blockIdx.x * 32;
#pragma unroll
    for (int r = 0; r < 32; r += 8)
        tile[threadIdx.y + r][threadIdx.x] =
            ip[(size_t)(i0 + threadIdx.y + r) * 512 + j0 + threadIdx.x];
    __syncthreads();
#pragma unroll
    for (int r = 0; r < 32; r += 8)
        op[(size_t)(j0 + threadIdx.y + r) * 512 + i0 + threadIdx.x] =
            tile[threadIdx.x][threadIdx.y + r];
}

// ---------------------------------------------------------------------------
// Mode mix: for each (h, mode): OUT[b][o] = sum_i X[b][i] * W[i][o]  (complex)
//   xs layout: row (b*512 + h*64 + i), cols 0..31 = re, 32..63 = im
//   w  layout: wr/wi[(h*64+i)*64*32 + o*32 + mode]
//   g  layout: row (b*512 + h*64 + o), cols 0..31 = re, 32..63 = im
// ---------------------------------------------------------------------------
__global__ void modemix_k(const float* __restrict__ xs, const float* __restrict__ wr,
                          const float* __restrict__ wi, float* __restrict__ g) {
    int mode = blockIdx.x, h = blockIdx.y;
    __shared__ float Xr[64][32], Xi[64][32], Wr[32][64], Wi[32][64];
    int tid = threadIdx.x;
    int tb = tid >> 4, to = tid & 15;

    float cr[4][4], ci[4][4];
#pragma unroll
    for (int a = 0; a < 4; a++)
#pragma unroll
        for (int c = 0; c < 4; c++) { cr[a][c] = 0.f; ci[a][c] = 0.f; }

    for (int i0 = 0; i0 < 64; i0 += 32) {
#pragma unroll
        for (int j = 0; j < 8; j++) {
            int e = tid * 8 + j;
            int b = e >> 5, ii = e & 31;
            size_t xrow = ((size_t)b * 512 + h * 64 + i0 + ii) * 64;
            Xr[b][ii] = xs[xrow + mode];
            Xi[b][ii] = xs[xrow + 32 + mode];
            int wi2 = e >> 6, o = e & 63;
            size_t widx = (((size_t)h * 64 + i0 + wi2) * 64 + o) * 32 + mode;
            Wr[wi2][o] = wr[widx];
            Wi[wi2][o] = wi[widx];
        }
        __syncthreads();
#pragma unroll 8
        for (int ii = 0; ii < 32; ii++) {
            float xr[4], xi4[4], wrv[4], wiv[4];
#pragma unroll
            for (int a = 0; a < 4; a++) { xr[a] = Xr[tb*4+a][ii]; xi4[a] = Xi[tb*4+a][ii]; }
#pragma unroll
            for (int c = 0; c < 4; c++) { wrv[c] = Wr[ii][to*4+c]; wiv[c] = Wi[ii][to*4+c]; }
#pragma unroll
            for (int a = 0; a < 4; a++)
#pragma unroll
                for (int c = 0; c < 4; c++) {
                    cr[a][c] += xr[a] * wrv[c] - xi4[a] * wiv[c];
                    ci[a][c] += xr[a] * wiv[c] + xi4[a] * wrv[c];
                }
        }
        __syncthreads();
    }

#pragma unroll
    for (int a = 0; a < 4; a++) {
        int b = tb * 4 + a;
#pragma unroll
        for (int c = 0; c < 4; c++) {
            int o = to * 4 + c;
            size_t base = ((size_t)b * 512 + h * 64 + o) * 64;
            g[base + mode] = cr[a][c];
            g[base + 32 + mode] = ci[a][c];
        }
    }
}

// ---------------------------------------------------------------------------
// Series decomposition: out = in - moving_avg_25(in)  (edge-clamped)
// ---------------------------------------------------------------------------
__global__ void decomp_k(const float* __restrict__ in, float* __restrict__ out) {
    int b = blockIdx.y, l = blockIdx.x, d = threadIdx.x;
    const float* base = in + (size_t)b * (LL * DDIM);
    float s = 0.f;
#pragma unroll
    for (int j = -12; j <= 12; j++) {
        int ll = l + j;
        ll = ll < 0 ? 0 : (ll > 511 ? 511 : ll);
        s += base[(size_t)ll * DDIM + d];
    }
    out[((size_t)b * LL + l) * DDIM + d] = base[(size_t)l * DDIM + d] - s * (1.0f / 25.0f);
}

// ---------------------------------------------------------------------------
// LayerNorm over D, then lastcat computes (xh[:, -1] - mean_L(xh)) ++ time_vecs
// ---------------------------------------------------------------------------
__device__ __forceinline__ float blocksum512(float v, float* red) {
    int lane = threadIdx.x & 31, w = threadIdx.x >> 5;
#pragma unroll
    for (int o = 16; o; o >>= 1) v += __shfl_down_sync(0xffffffffu, v, o);
    if (lane == 0) red[w] = v;
    __syncthreads();
    if (w == 0) {
        float t = (lane < 16) ? red[lane] : 0.f;
#pragma unroll
        for (int o = 8; o; o >>= 1) t += __shfl_down_sync(0xffffffffu, t, o);
        if (lane == 0) red[0] = t;
    }
    __syncthreads();
    float r = red[0];
    __syncthreads();
    return r;
}

__global__ void layernorm_k(const float* __restrict__ x, const float* __restrict__ w,
                            const float* __restrict__ bb, float* __restrict__ xh) {
    __shared__ float red[32];
    int b = blockIdx.y, l = blockIdx.x, d = threadIdx.x;
    size_t base = ((size_t)b * LL + l) * DDIM;
    float v = x[base + d];
    float mu = blocksum512(v, red) * (1.f / 512.f);
    float dv = v - mu;
    float var = blocksum512(dv * dv, red) * (1.f / 512.f);
    xh[base + d] = dv * rsqrtf(var + 1e-5f) * w[d] + bb[d];
}

__global__ void lastcat_k(const float* __restrict__ xh, const float* __restrict__ time_vecs,
                          float* __restrict__ cat) {
    int b = blockIdx.x, d = threadIdx.x;
    float s = 0.f;
    for (int l = 0; l < LL; l++) s += xh[((size_t)b * LL + l) * DDIM + d];
    cat[b * KCAT + d] = xh[((size_t)b * LL + 511) * DDIM + d] - s * (1.f / 512.f);
    if (d < 24) cat[b * KCAT + 512 + d] = time_vecs[((size_t)b * LL + 511) * 24 + d];
}

// ---------------------------------------------------------------------------
// Host orchestration
// ---------------------------------------------------------------------------
extern "C" void kernel_launch(void* const* d_in, const int* in_sizes, int n_in,
                              void* d_out, int out_size) {
    (void)in_sizes; (void)n_in; (void)out_size;
    const int*   x_app     = (const int*)  d_in[0];
    const float* x_time    = (const float*)d_in[1];
    const float* time_vecs = (const float*)d_in[2];
    /* d_in[3] = targets (unused by reference) */
    const float* emb       = (const float*)d_in[4];
    const float* time_w    = (const float*)d_in[5];
    const float* time_b    = (const float*)d_in[6];
    const float* Wq        = (const float*)d_in[7];
    const float* bq        = (const float*)d_in[8];
    const float* Wo        = (const float*)d_in[9];
    const float* bo        = (const float*)d_in[10];
    const float* four_wr   = (const float*)d_in[11];
    const float* four_wi   = (const float*)d_in[12];
    const float* conv1     = (const float*)d_in[13];
    const float* conv2     = (const float*)d_in[14];
    const float* norm_w    = (const float*)d_in[15];
    const float* norm_b    = (const float*)d_in[16];
    const float* proj_w    = (const float*)d_in[17];
    const float* proj_b    = (const float*)d_in[18];

    float *gx, *gq, *gt1, *gt2, *gy, *gtw, *gitw, *gcat;
    cudaGetSymbolAddress((void**)&gx,   g_x);
    cudaGetSymbolAddress((void**)&gq,   g_q);
    cudaGetSymbolAddress((void**)&gt1,  g_t1);
    cudaGetSymbolAddress((void**)&gt2,  g_t2);
    cudaGetSymbolAddress((void**)&gy,   g_y);
    cudaGetSymbolAddress((void**)&gtw,  g_tw);
    cudaGetSymbolAddress((void**)&gitw, g_itw);
    cudaGetSymbolAddress((void**)&gcat, g_cat);

    const int M = BB * LL;   // 32768

    init_tw_k<<<64, 512>>>(gtw, gitw);
    embed_k<<<dim3(LL, BB), DDIM>>>(x_app, x_time, emb, time_w, time_b, gx);

    dim3 tgrid(16, 16, BB), tblk(32, 8);
    for (int l = 0; l < 2; l++) {
        const float* Wql = Wq + (size_t)l * DDIM * DDIM;
        const float* bql = bq + (size_t)l * DDIM;
        const float* Wol = Wo + (size_t)l * DDIM * DDIM;
        const float* bol = bo + (size_t)l * DDIM;
        const float* wrl = four_wr + (size_t)l * HH * EE * EE * NMODES;
        const float* wil = four_wi + (size_t)l * HH * EE * EE * NMODES;
        const float* c1l = conv1 + (size_t)l * DFF * DDIM;
        const float* c2l = conv2 + (size_t)l * DDIM * DFF;

        // q = x @ Wq^T + bq
        launch_gemm(gx, Wql, bql, nullptr, gq, M, DDIM, DDIM, false, false);
        // qT[b][hi][l] <- q[b][l][hi]
        transpose512_k<<<tgrid, tblk>>>(gq, gt1);
        // forward DFT (32 modes re+im): xs = qT @ TW^T
        launch_gemm(gt1, gtw, nullptr, nullptr, gt2, M, 64, DDIM, false, false);
        // complex mode mixing
        modemix_k<<<dim3(NMODES, HH), 256>>>(gt2, wrl, wil, gt1);
        // inverse DFT: foutT = g @ ITW^T
        launch_gemm(gt1, gitw, nullptr, nullptr, gq, M, DDIM, 64, false, false);
        // fout[b][l][hi] <- foutT[b][hi][l]
        transpose512_k<<<tgrid, tblk>>>(gq, gt1);
        // tmp = fout @ Wo^T + bo + x
        launch_gemm(gt1, Wol, bol, gx, gt2, M, DDIM, DDIM, false, true);
        // x = tmp - movavg(tmp)
        decomp_k<<<dim3(LL, BB), DDIM>>>(gt2, gx);
        // y = relu(x @ c1^T)
        launch_gemm(gx, c1l, nullptr, nullptr, gy, M, DFF, DDIM, true, false);
        // tmp = y @ c2^T + x
        launch_gemm(gy, c2l, nullptr, gx, gt2, M, DDIM, DFF, false, true);
        // x = tmp - movavg(tmp)
        decomp_k<<<dim3(LL, BB), DDIM>>>(gt2, gx);
    }

    // final layernorm + last-token extraction
    layernorm_k<<<dim3(LL, BB), DDIM>>>(gx, norm_w, norm_b, gq);
    lastcat_k<<<BB, DDIM>>>(gq, time_vecs, gcat);
    // score = cat @ proj_w^T + proj_b
    launch_gemm(gcat, proj_w, proj_b, nullptr, (float*)d_out, BB, NAPP, KCAT, false, false);
}

// round 3
// speedup vs baseline: 2.5547x; 2.5547x over previous
#include <cuda_runtime.h>
#include <cuda_bf16.h>
#include <math.h>
#include <stdint.h>

// Problem constants
#define BB    64
#define LL    512
#define DDIM  512
#define HH    8
#define EE    64
#define DFF   2048
#define NMODES 32
#define NAPP  10000
#define KCAT  536    // D + 24
#define TWOPI 6.283185307179586476925286766559

// ---------------------------------------------------------------------------
// Scratch (device globals — no runtime allocation allowed)
// ---------------------------------------------------------------------------
__device__ __align__(128) float g_x [BB*LL*DDIM];
__device__ __align__(128) float g_q [BB*LL*DDIM];
__device__ __align__(128) float g_t1[BB*LL*DDIM];
__device__ __align__(128) float g_t2[BB*LL*DDIM];
__device__ __align__(128) float g_y [BB*LL*DFF];
__device__ __align__(128) float g_cat[BB*KCAT];

// bf16 hi/lo planes for weights & twiddles
__device__ __align__(128) __nv_bfloat16 g_wqh[2*DDIM*DDIM], g_wql[2*DDIM*DDIM];
__device__ __align__(128) __nv_bfloat16 g_woh[2*DDIM*DDIM], g_wol[2*DDIM*DDIM];
__device__ __align__(128) __nv_bfloat16 g_c1h[2*DFF*DDIM],  g_c1l[2*DFF*DDIM];
__device__ __align__(128) __nv_bfloat16 g_c2h[2*DDIM*DFF],  g_c2l[2*DDIM*DFF];
__device__ __align__(128) __nv_bfloat16 g_twh[128*512],     g_twl[128*512];   // fwd DFT, padded to 128 rows
__device__ __align__(128) __nv_bfloat16 g_itwh[512*64],     g_itwl[512*64];   // inv DFT

// ---------------------------------------------------------------------------
// PTX helpers (arch-portable: ldmatrix / mma.sync / cp.async only)
// ---------------------------------------------------------------------------
__device__ __forceinline__ uint32_t smem_u32(const void* p) {
    uint32_t a;
    asm("{ .reg .u64 t; cvta.to.shared.u64 t, %1; cvt.u32.u64 %0, t; }" : "=r"(a) : "l"(p));
    return a;
}
#define CP16(d, s)  asm volatile("cp.async.cg.shared.global [%0], [%1], 16;" :: "r"(d), "l"(s) : "memory")
#define CP_COMMIT() asm volatile("cp.async.commit_group;" ::: "memory")
#define CP_WAIT0()  asm volatile("cp.async.wait_group 0;" ::: "memory")

#define LDSM4(r0, r1, r2, r3, a) \
    asm volatile("ldmatrix.sync.aligned.m8n8.x4.shared.b16 {%0,%1,%2,%3}, [%4];" \
        : "=r"(r0), "=r"(r1), "=r"(r2), "=r"(r3) : "r"(a))

#define MMA16816(c, a0, a1, a2, a3, b0, b1) \
    asm volatile("mma.sync.aligned.m16n8k16.row.col.f32.bf16.bf16.f32 " \
        "{%0,%1,%2,%3}, {%4,%5,%6,%7}, {%8,%9}, {%0,%1,%2,%3};" \
        : "+f"((c)[0]), "+f"((c)[1]), "+f"((c)[2]), "+f"((c)[3]) \
        : "r"(a0), "r"(a1), "r"(a2), "r"(a3), "r"(b0), "r"(b1))

// ---------------------------------------------------------------------------
// Tensor-core GEMM: C[m,n] = sum_k A[m,k]*B[n,k]  (+bias[n]) (+Cin) (relu)
//   A: f32 [M,K] (M mult of 128). B: bf16 hi/lo planes [Npad,K] (Npad mult 128).
//   Split-3: acc = Ah*Bh + Al*Bh + Ah*Bl (fp32 accum).
//   Tile 128x128, BK=32, 256 threads, double-buffered. K mult of 32.
//   SMEM rows padded to 80B pitch (40 bf16) -> conflict-free ldmatrix.
// ---------------------------------------------------------------------------
#define MG_PITCH 80
#define MG_PLANE (128 * MG_PITCH)       // 10240 B
#define MG_AH 0
#define MG_AL (1 * MG_PLANE)
#define MG_BH (2 * MG_PLANE)
#define MG_BL (3 * MG_PLANE)
#define MG_STAGE (4 * MG_PLANE)         // 40960 B
#define MG_SMEM (2 * MG_STAGE)          // 81920 B

template <int RELU, int ADDC, int BIAS>
__global__ void __launch_bounds__(256, 1)
mgemm_k(const float* __restrict__ A, const __nv_bfloat16* __restrict__ Bh,
        const __nv_bfloat16* __restrict__ Bl, const float* __restrict__ bias,
        const float* __restrict__ Cin, float* __restrict__ C,
        int K, int Nout) {
    extern __shared__ __align__(128) char smem[];
    const uint32_t sb = smem_u32(smem);
    const int tid = threadIdx.x, lane = tid & 31, wid = tid >> 5;
    const int wm = wid & 3, wn = wid >> 2;           // warp grid 4 x 2
    const int m0 = blockIdx.y * 128, n0 = blockIdx.x * 128;

    float acc[2][8][4];
#pragma unroll
    for (int i = 0; i < 2; i++)
#pragma unroll
        for (int j = 0; j < 8; j++)
#pragma unroll
            for (int t = 0; t < 4; t++) acc[i][j][t] = 0.f;

    // ldmatrix lane addressing (within stage, byte offsets)
    const uint32_t a_off = (uint32_t)((wm * 32 + (lane & 7) + ((lane >> 3) & 1) * 8) * MG_PITCH
                                      + (lane >> 4) * 16);
    const uint32_t b_off = (uint32_t)((wn * 64 + ((lane >> 4) & 1) * 8 + (lane & 7)) * MG_PITCH
                                      + ((lane >> 3) & 1) * 16);

    float ar[16];

    auto ldA = [&](int c) {
#pragma unroll
        for (int j = 0; j < 2; j++) {
            int idx = j * 256 + tid;
            int r = idx >> 2, ch = idx & 3;
            const float* p = A + (size_t)(m0 + r) * K + c * 32 + ch * 8;
            float4 v0 = *(const float4*)p;
            float4 v1 = *(const float4*)(p + 4);
            ar[j*8+0] = v0.x; ar[j*8+1] = v0.y; ar[j*8+2] = v0.z; ar[j*8+3] = v0.w;
            ar[j*8+4] = v1.x; ar[j*8+5] = v1.y; ar[j*8+6] = v1.z; ar[j*8+7] = v1.w;
        }
    };
    auto stsA = [&](int s) {
        char* base = smem + s * MG_STAGE;
#pragma unroll
        for (int j = 0; j < 2; j++) {
            int idx = j * 256 + tid;
            int r = idx >> 2, ch = idx & 3;
            uint32_t h[4], l[4];
#pragma unroll
            for (int t = 0; t < 4; t++) {
                float f0 = ar[j*8 + 2*t], f1 = ar[j*8 + 2*t + 1];
                __nv_bfloat162 hh = __floats2bfloat162_rn(f0, f1);
                float r0 = f0 - __bfloat162float(hh.x);
                float r1 = f1 - __bfloat162float(hh.y);
                __nv_bfloat162 ll = __floats2bfloat162_rn(r0, r1);
                h[t] = *(uint32_t*)&hh;
                l[t] = *(uint32_t*)&ll;
            }
            uint32_t off = (uint32_t)(r * MG_PITCH + ch * 16);
            *(uint4*)(base + MG_AH + off) = make_uint4(h[0], h[1], h[2], h[3]);
            *(uint4*)(base + MG_AL + off) = make_uint4(l[0], l[1], l[2], l[3]);
        }
    };
    auto cpB = [&](int c, int s) {
        uint32_t base = sb + s * MG_STAGE;
#pragma unroll
        for (int j = 0; j < 4; j++) {
            int idx = j * 256 + tid;
            int pl = idx >> 9, r = (idx >> 2) & 127, ch = idx & 3;
            const __nv_bfloat16* src = (pl ? Bl : Bh) + (size_t)(n0 + r) * K + c * 32 + ch * 8;
            uint32_t dst = base + (pl ? MG_BL : MG_BH) + (uint32_t)(r * MG_PITCH + ch * 16);
            CP16(dst, src);
        }
    };

    const int NC = K >> 5;

    // prologue: stage 0
    ldA(0);
    cpB(0, 0);
    CP_COMMIT();
    stsA(0);

    for (int c = 0; c < NC; c++) {
        const int s = c & 1;
        CP_WAIT0();
        __syncthreads();
        if (c + 1 < NC) {
            ldA(c + 1);          // LDG latency hidden behind MMA below
            cpB(c + 1, s ^ 1);
            CP_COMMIT();
        }
        const uint32_t base = sb + s * MG_STAGE;
#pragma unroll
        for (int ks = 0; ks < 2; ks++) {
            const uint32_t koff = ks * 32;
            uint32_t ah[2][4], al[2][4];
#pragma unroll
            for (int mi = 0; mi < 2; mi++) {
                LDSM4(ah[mi][0], ah[mi][1], ah[mi][2], ah[mi][3],
                      base + MG_AH + a_off + mi * (16 * MG_PITCH) + koff);
                LDSM4(al[mi][0], al[mi][1], al[mi][2], al[mi][3],
                      base + MG_AL + a_off + mi * (16 * MG_PITCH) + koff);
            }
#pragma unroll
            for (int np = 0; np < 4; np++) {
                uint32_t bh[4], bl[4];
                LDSM4(bh[0], bh[1], bh[2], bh[3],
                      base + MG_BH + b_off + np * (16 * MG_PITCH) + koff);
                LDSM4(bl[0], bl[1], bl[2], bl[3],
                      base + MG_BL + b_off + np * (16 * MG_PITCH) + koff);
#pragma unroll
                for (int mi = 0; mi < 2; mi++) {
#pragma unroll
                    for (int t = 0; t < 2; t++) {
                        float* cc = acc[mi][np * 2 + t];
                        MMA16816(cc, ah[mi][0], ah[mi][1], ah[mi][2], ah[mi][3],
                                 bh[2*t], bh[2*t + 1]);
                        MMA16816(cc, al[mi][0], al[mi][1], al[mi][2], al[mi][3],
                                 bh[2*t], bh[2*t + 1]);
                        MMA16816(cc, ah[mi][0], ah[mi][1], ah[mi][2], ah[mi][3],
                                 bl[2*t], bl[2*t + 1]);
                    }
                }
            }
        }
        if (c + 1 < NC) stsA(s ^ 1);
    }

    // epilogue
#pragma unroll
    for (int mi = 0; mi < 2; mi++) {
        const int r0 = m0 + wm * 32 + mi * 16 + (lane >> 2);
#pragma unroll
        for (int ni = 0; ni < 8; ni++) {
            const int col = n0 + wn * 64 + ni * 8 + 2 * (lane & 3);
            if (col >= Nout) continue;
            float v00 = acc[mi][ni][0], v01 = acc[mi][ni][1];
            float v10 = acc[mi][ni][2], v11 = acc[mi][ni][3];
            if (BIAS) {
                float2 bv = *(const float2*)&bias[col];
                v00 += bv.x; v01 += bv.y; v10 += bv.x; v11 += bv.y;
            }
            const size_t o0 = (size_t)r0 * Nout + col;
            const size_t o1 = (size_t)(r0 + 8) * Nout + col;
            if (ADDC) {
                float2 c0 = *(const float2*)&Cin[o0];
                float2 c1 = *(const float2*)&Cin[o1];
                v00 += c0.x; v01 += c0.y; v10 += c1.x; v11 += c1.y;
            }
            if (RELU) {
                v00 = fmaxf(v00, 0.f); v01 = fmaxf(v01, 0.f);
                v10 = fmaxf(v10, 0.f); v11 = fmaxf(v11, 0.f);
            }
            *(float2*)&C[o0] = make_float2(v00, v01);
            *(float2*)&C[o1] = make_float2(v10, v11);
        }
    }
}

template <int R, int AD, int BI>
static void mg_launch(const float* A, const __nv_bfloat16* Bhh, const __nv_bfloat16* Bll,
                      const float* bias, const float* Cin, float* C,
                      int M, int Npad, int K, int Nout) {
    static bool done = false;
    cudaFuncSetAttribute(mgemm_k<R, AD, BI>, cudaFuncAttributeMaxDynamicSharedMemorySize, MG_SMEM);
    (void)done;
    dim3 g(Npad / 128, M / 128);
    mgemm_k<R, AD, BI><<<g, 256, MG_SMEM>>>(A, Bhh, Bll, bias, Cin, C, K, Nout);
}

// ---------------------------------------------------------------------------
// Weight split + twiddle init
// ---------------------------------------------------------------------------
__global__ void split_k(const float* __restrict__ s, __nv_bfloat16* __restrict__ h,
                        __nv_bfloat16* __restrict__ l, int n) {
    int i = blockIdx.x * blockDim.x + threadIdx.x;
    if (i < n) {
        float v = s[i];
        __nv_bfloat16 hh = __float2bfloat16(v);
        h[i] = hh;
        l[i] = __float2bfloat16(v - __bfloat162float(hh));
    }
}

__global__ void init_tw_k(__nv_bfloat16* twh, __nv_bfloat16* twl,
                          __nv_bfloat16* itwh, __nv_bfloat16* itwl) {
    int i = blockIdx.x * blockDim.x + threadIdx.x;   // 0..65535
    {
        int c = i >> 9, l = i & 511;
        double v = 0.0;
        if (c < 32)       v = cos((TWOPI / 512.0) * (double)(l * c));
        else if (c < 64)  v = -sin((TWOPI / 512.0) * (double)(l * (c - 32)));
        float f = (float)v;
        __nv_bfloat16 hh = __float2bfloat16(f);
        twh[i] = hh;
        twl[i] = __float2bfloat16(f - __bfloat162float(hh));
    }
    if (i < 512 * 64) {
        int l = i >> 6, c = i & 63;
        double v;
        if (c == 0)       v = 1.0 / 512.0;
        else if (c < 32)  v = 2.0 * cos((TWOPI / 512.0) * (double)(l * c)) / 512.0;
        else if (c == 32) v = 0.0;
        else              v = -2.0 * sin((TWOPI / 512.0) * (double)(l * (c - 32))) / 512.0;
        float f = (float)v;
        __nv_bfloat16 hh = __float2bfloat16(f);
        itwh[i] = hh;
        itwl[i] = __float2bfloat16(f - __bfloat162float(hh));
    }
}

// ---------------------------------------------------------------------------
// Embedding
// ---------------------------------------------------------------------------
__global__ void embed_k(const int* __restrict__ x_app, const float* __restrict__ x_time,
                        const float* __restrict__ emb, const float* __restrict__ tw,
                        const float* __restrict__ tb, float* __restrict__ x) {
    int b = blockIdx.y, l = blockIdx.x, d = threadIdx.x;
    int a = x_app[b * LL + l];
    float t = x_time[b * LL + l];
    x[((size_t)b * LL + l) * DDIM + d] = emb[(size_t)a * DDIM + d] + t * tw[d] + tb[d];
}

// ---------------------------------------------------------------------------
// fp32 SIMT GEMM (final projection only: K=536)
// ---------------------------------------------------------------------------
__global__ __launch_bounds__(256, 2)
void gemm_nt_kernel(const float* __restrict__ A, const float* __restrict__ Bm,
                    const float* __restrict__ bias, float* __restrict__ Cout,
                    int M, int N, int K) {
    __shared__ float As[8][128];
    __shared__ float Bs[8][128];
    const int tid = threadIdx.x;
    const int m0 = blockIdx.y * 128, n0 = blockIdx.x * 128;
    const int lr = tid >> 1, lk = (tid & 1) * 4;
    const int tx = tid & 15, ty = tid >> 4;
    const int arow = m0 + lr, brow = n0 + lr;
    const bool aval = arow < M, bval = brow < N;
    const float* Ap = A + (size_t)arow * K + lk;
    const float* Bp = Bm + (size_t)brow * K + lk;
    float acc[8][8];
#pragma unroll
    for (int i = 0; i < 8; i++)
#pragma unroll
        for (int j = 0; j < 8; j++) acc[i][j] = 0.f;
    const float4 z4 = make_float4(0.f, 0.f, 0.f, 0.f);
    for (int k0 = 0; k0 < K; k0 += 8) {
        float4 a = z4, b = z4;
        if (aval && lk + k0 < K) a = *(const float4*)Ap;
        if (bval && lk + k0 < K) b = *(const float4*)Bp;
        Ap += 8; Bp += 8;
        __syncthreads();
        As[lk+0][lr]=a.x; As[lk+1][lr]=a.y; As[lk+2][lr]=a.z; As[lk+3][lr]=a.w;
        Bs[lk+0][lr]=b.x; Bs[lk+1][lr]=b.y; Bs[lk+2][lr]=b.z; Bs[lk+3][lr]=b.w;
        __syncthreads();
#pragma unroll
        for (int k = 0; k < 8; k++) {
            float arv[8], brv[8];
            *(float4*)&arv[0] = *(const float4*)&As[k][ty*8];
            *(float4*)&arv[4] = *(const float4*)&As[k][ty*8+4];
            *(float4*)&brv[0] = *(const float4*)&Bs[k][tx*8];
            *(float4*)&brv[4] = *(const float4*)&Bs[k][tx*8+4];
#pragma unroll
            for (int i = 0; i < 8; i++)
#pragma unroll
                for (int j = 0; j < 8; j++) acc[i][j] += arv[i] * brv[j];
        }
    }
#pragma unroll
    for (int i = 0; i < 8; i++) {
        int m = m0 + ty * 8 + i;
        if (m >= M) continue;
        size_t row = (size_t)m * N;
#pragma unroll
        for (int jg = 0; jg < 8; jg++) {
            int n = n0 + tx * 8 + jg;
            if (n >= N) continue;
            Cout[row + n] = acc[i][jg] + bias[n];
        }
    }
}

// ---------------------------------------------------------------------------
// Per-batch 512x512 transpose
// ---------------------------------------------------------------------------
__global__ void transpose512_k(const float* __restrict__ in, float* __restrict__ out) {
    __shared__ float tile[32][33];
    int b = blockIdx.z;
    const float* ip = in + (size_t)b * (512 * 512);
    float* op = out + (size_t)b * (512 * 512);
    int i0 = blockIdx.y * 32, j0 = blockIdx.x * 32;
#pragma unroll
    for (int r = 0; r < 32; r += 8)
        tile[threadIdx.y + r][threadIdx.x] =
            ip[(size_t)(i0 + threadIdx.y + r) * 512 + j0 + threadIdx.x];
    __syncthreads();
#pragma unroll
    for (int r = 0; r < 32; r += 8)
        op[(size_t)(j0 + threadIdx.y + r) * 512 + i0 + threadIdx.x] =
            tile[threadIdx.x][threadIdx.y + r];
}

// ---------------------------------------------------------------------------
// Complex mode mixing (per head & mode): OUT[b][o] = sum_i X[b][i] * W[i][o]
// ---------------------------------------------------------------------------
__global__ void modemix_k(const float* __restrict__ xs, const float* __restrict__ wr,
                          const float* __restrict__ wi, float* __restrict__ g) {
    int mode = blockIdx.x, h = blockIdx.y;
    __shared__ float Xr[64][32], Xi[64][32], Wr[32][64], Wi[32][64];
    int tid = threadIdx.x;
    int tb = tid >> 4, to = tid & 15;
    float cr[4][4], ci[4][4];
#pragma unroll
    for (int a = 0; a < 4; a++)
#pragma unroll
        for (int c = 0; c < 4; c++) { cr[a][c] = 0.f; ci[a][c] = 0.f; }
    for (int i0 = 0; i0 < 64; i0 += 32) {
#pragma unroll
        for (int j = 0; j < 8; j++) {
            int e = tid * 8 + j;
            int b = e >> 5, ii = e & 31;
            size_t xrow = ((size_t)b * 512 + h * 64 + i0 + ii) * 64;
            Xr[b][ii] = xs[xrow + mode];
            Xi[b][ii] = xs[xrow + 32 + mode];
            int wi2 = e >> 6, o = e & 63;
            size_t widx = (((size_t)h * 64 + i0 + wi2) * 64 + o) * 32 + mode;
            Wr[wi2][o] = wr[widx];
            Wi[wi2][o] = wi[widx];
        }
        __syncthreads();
#pragma unroll 8
        for (int ii = 0; ii < 32; ii++) {
            float xr[4], xi4[4], wrv[4], wiv[4];
#pragma unroll
            for (int a = 0; a < 4; a++) { xr[a] = Xr[tb*4+a][ii]; xi4[a] = Xi[tb*4+a][ii]; }
#pragma unroll
            for (int c = 0; c < 4; c++) { wrv[c] = Wr[ii][to*4+c]; wiv[c] = Wi[ii][to*4+c]; }
#pragma unroll
            for (int a = 0; a < 4; a++)
#pragma unroll
                for (int c = 0; c < 4; c++) {
                    cr[a][c] += xr[a] * wrv[c] - xi4[a] * wiv[c];
                    ci[a][c] += xr[a] * wiv[c] + xi4[a] * wrv[c];
                }
        }
        __syncthreads();
    }
#pragma unroll
    for (int a = 0; a < 4; a++) {
        int b = tb * 4 + a;
#pragma unroll
        for (int c = 0; c < 4; c++) {
            int o = to * 4 + c;
            size_t base = ((size_t)b * 512 + h * 64 + o) * 64;
            g[base + mode] = cr[a][c];
            g[base + 32 + mode] = ci[a][c];
        }
    }
}

// ---------------------------------------------------------------------------
// Series decomposition: out = in - moving_avg_25(in)
// ---------------------------------------------------------------------------
__global__ void decomp_k(const float* __restrict__ in, float* __restrict__ out) {
    int b = blockIdx.y, l = blockIdx.x, d = threadIdx.x;
    const float* base = in + (size_t)b * (LL * DDIM);
    float s = 0.f;
#pragma unroll
    for (int j = -12; j <= 12; j++) {
        int ll = l + j;
        ll = ll < 0 ? 0 : (ll > 511 ? 511 : ll);
        s += base[(size_t)ll * DDIM + d];
    }
    out[((size_t)b * LL + l) * DDIM + d] = base[(size_t)l * DDIM + d] - s * (1.0f / 25.0f);
}

// ---------------------------------------------------------------------------
// LayerNorm + last-token concat
// ---------------------------------------------------------------------------
__device__ __forceinline__ float blocksum512(float v, float* red) {
    int lane = threadIdx.x & 31, w = threadIdx.x >> 5;
#pragma unroll
    for (int o = 16; o; o >>= 1) v += __shfl_down_sync(0xffffffffu, v, o);
    if (lane == 0) red[w] = v;
    __syncthreads();
    if (w == 0) {
        float t = (lane < 16) ? red[lane] : 0.f;
#pragma unroll
        for (int o = 8; o; o >>= 1) t += __shfl_down_sync(0xffffffffu, t, o);
        if (lane == 0) red[0] = t;
    }
    __syncthreads();
    float r = red[0];
    __syncthreads();
    return r;
}

__global__ void layernorm_k(const float* __restrict__ x, const float* __restrict__ w,
                            const float* __restrict__ bb, float* __restrict__ xh) {
    __shared__ float red[32];
    int b = blockIdx.y, l = blockIdx.x, d = threadIdx.x;
    size_t base = ((size_t)b * LL + l) * DDIM;
    float v = x[base + d];
    float mu = blocksum512(v, red) * (1.f / 512.f);
    float dv = v - mu;
    float var = blocksum512(dv * dv, red) * (1.f / 512.f);
    xh[base + d] = dv * rsqrtf(var + 1e-5f) * w[d] + bb[d];
}

__global__ void lastcat_k(const float* __restrict__ xh, const float* __restrict__ time_vecs,
                          float* __restrict__ cat) {
    int b = blockIdx.x, d = threadIdx.x;
    float s = 0.f;
    for (int l = 0; l < LL; l++) s += xh[((size_t)b * LL + l) * DDIM + d];
    cat[b * KCAT + d] = xh[((size_t)b * LL + 511) * DDIM + d] - s * (1.f / 512.f);
    if (d < 24) cat[b * KCAT + 512 + d] = time_vecs[((size_t)b * LL + 511) * 24 + d];
}

// ---------------------------------------------------------------------------
// Host orchestration
// ---------------------------------------------------------------------------
extern "C" void kernel_launch(void* const* d_in, const int* in_sizes, int n_in,
                              void* d_out, int out_size) {
    (void)in_sizes; (void)n_in; (void)out_size;
    const int*   x_app     = (const int*)  d_in[0];
    const float* x_time    = (const float*)d_in[1];
    const float* time_vecs = (const float*)d_in[2];
    const float* emb       = (const float*)d_in[4];
    const float* time_w    = (const float*)d_in[5];
    const float* time_b    = (const float*)d_in[6];
    const float* Wq        = (const float*)d_in[7];
    const float* bq        = (const float*)d_in[8];
    const float* Wo        = (const float*)d_in[9];
    const float* bo        = (const float*)d_in[10];
    const float* four_wr   = (const float*)d_in[11];
    const float* four_wi   = (const float*)d_in[12];
    const float* conv1     = (const float*)d_in[13];
    const float* conv2     = (const float*)d_in[14];
    const float* norm_w    = (const float*)d_in[15];
    const float* norm_b    = (const float*)d_in[16];
    const float* proj_w    = (const float*)d_in[17];
    const float* proj_b    = (const float*)d_in[18];

    float *gx, *gq, *gt1, *gt2, *gy, *gcat;
    __nv_bfloat16 *wqh, *wql, *woh, *wol, *c1h, *c1l, *c2h, *c2l, *twh, *twl, *itwh, *itwl;
    cudaGetSymbolAddress((void**)&gx,   g_x);
    cudaGetSymbolAddress((void**)&gq,   g_q);
    cudaGetSymbolAddress((void**)&gt1,  g_t1);
    cudaGetSymbolAddress((void**)&gt2,  g_t2);
    cudaGetSymbolAddress((void**)&gy,   g_y);
    cudaGetSymbolAddress((void**)&gcat, g_cat);
    cudaGetSymbolAddress((void**)&wqh,  g_wqh);  cudaGetSymbolAddress((void**)&wql, g_wql);
    cudaGetSymbolAddress((void**)&woh,  g_woh);  cudaGetSymbolAddress((void**)&wol, g_wol);
    cudaGetSymbolAddress((void**)&c1h,  g_c1h);  cudaGetSymbolAddress((void**)&c1l, g_c1l);
    cudaGetSymbolAddress((void**)&c2h,  g_c2h);  cudaGetSymbolAddress((void**)&c2l, g_c2l);
    cudaGetSymbolAddress((void**)&twh,  g_twh);  cudaGetSymbolAddress((void**)&twl, g_twl);
    cudaGetSymbolAddress((void**)&itwh, g_itwh); cudaGetSymbolAddress((void**)&itwl, g_itwl);

    const int M = BB * LL;   // 32768

    init_tw_k<<<256, 256>>>(twh, twl, itwh, itwl);
    split_k<<<(2*DDIM*DDIM + 255)/256, 256>>>(Wq, wqh, wql, 2*DDIM*DDIM);
    split_k<<<(2*DDIM*DDIM + 255)/256, 256>>>(Wo, woh, wol, 2*DDIM*DDIM);
    split_k<<<(2*DFF*DDIM + 255)/256, 256>>>(conv1, c1h, c1l, 2*DFF*DDIM);
    split_k<<<(2*DDIM*DFF + 255)/256, 256>>>(conv2, c2h, c2l, 2*DDIM*DFF);

    embed_k<<<dim3(LL, BB), DDIM>>>(x_app, x_time, emb, time_w, time_b, gx);

    dim3 tgrid(16, 16, BB), tblk(32, 8);
    for (int l = 0; l < 2; l++) {
        const float* bql = bq + (size_t)l * DDIM;
        const float* bol = bo + (size_t)l * DDIM;
        const float* wrl = four_wr + (size_t)l * HH * EE * EE * NMODES;
        const float* wil = four_wi + (size_t)l * HH * EE * EE * NMODES;
        size_t owq = (size_t)l * DDIM * DDIM;
        size_t oc1 = (size_t)l * DFF * DDIM;
        size_t oc2 = (size_t)l * DDIM * DFF;

        // q = x @ Wq^T + bq
        mg_launch<0,0,1>(gx, wqh + owq, wql + owq, bql, nullptr, gq, M, 512, 512, 512);
        transpose512_k<<<tgrid, tblk>>>(gq, gt1);
        // forward DFT (32 modes re+im): xs = qT @ TW^T  (twiddles padded to 128 rows)
        mg_launch<0,0,0>(gt1, twh, twl, nullptr, nullptr, gt2, M, 128, 512, 64);
        modemix_k<<<dim3(NMODES, HH), 256>>>(gt2, wrl, wil, gt1);
        // inverse DFT: foutT = g @ ITW^T
        mg_launch<0,0,0>(gt1, itwh, itwl, nullptr, nullptr, gq, M, 512, 64, 512);
        transpose512_k<<<tgrid, tblk>>>(gq, gt1);
        // tmp = fout @ Wo^T + bo + x
        mg_launch<0,1,1>(gt1, woh + owq, wol + owq, bol, gx, gt2, M, 512, 512, 512);
        decomp_k<<<dim3(LL, BB), DDIM>>>(gt2, gx);
        // y = relu(x @ c1^T)
        mg_launch<1,0,0>(gx, c1h + oc1, c1l + oc1, nullptr, nullptr, gy, M, 2048, 512, 2048);
        // tmp = y @ c2^T + x
        mg_launch<0,1,0>(gy, c2h + oc2, c2l + oc2, nullptr, gx, gt2, M, 512, 2048, 512);
        decomp_k<<<dim3(LL, BB), DDIM>>>(gt2, gx);
    }

    layernorm_k<<<dim3(LL, BB), DDIM>>>(gx, norm_w, norm_b, gq);
    lastcat_k<<<BB, DDIM>>>(gq, time_vecs, gcat);
    gemm_nt_kernel<<<dim3((NAPP + 127) / 128, 1), 256>>>(gcat, proj_w, proj_b,
                                                         (float*)d_out, BB, NAPP, KCAT);
}